// round 13
// baseline (speedup 1.0000x reference)
#include <cuda_runtime.h>
#include <cstdint>

#define NN 100000
#define EE 600000
#define HH 128
#define GG 64
#define NGRP (NN / 16)        // 6250 row-groups of 16
#define WSTRIDE 144           // smem stride (floats): 144 % 32 == 16 -> conflict-free LDS.128
#define DEGCAP 64             // padded-CSR capacity per dst
#define GPAD 32               // 128B padding stride for global stat bins

// ---- scratch (__device__ globals; no allocs allowed) ----
__device__ float d_agg[(size_t)NN * HH];          // 51.2 MB: (1+eps)*node + sum(neigh)
__device__ float d_h3 [(size_t)NN * HH];          // 51.2 MB
__device__ int   d_cnt[NN];                       // per-dst degree counters
__device__ int   d_csr[(size_t)NN * DEGCAP];      // 25.6 MB padded src lists
__device__ float d_gbuf[3 * GG * GPAD];           // padded: [idx*GPAD] = gsum|gsq|gcnt
__device__ float d_gmean[GG];
__device__ float d_grstd[GG];

// ============================================================
// K1b: scatter edges into padded CSR buckets (int atomics only)
// ============================================================
__global__ void k1b_bucket(const int* __restrict__ ei) {
    int e = blockIdx.x * blockDim.x + threadIdx.x;
    if (e >= EE) return;
    int s = ei[e];
    int d = ei[EE + e];
    if ((unsigned)s >= NN || (unsigned)d >= NN) return;
    int slot = atomicAdd(&d_cnt[d], 1);
    if (slot < DEGCAP) d_csr[(size_t)d * DEGCAP + slot] = s;
}

// ============================================================
// K1c: per-dst gather-sum (warp per node, no float atomics)
// ============================================================
__global__ void k1c_gather(const float* __restrict__ node,
                           const float* __restrict__ epsp) {
    int warp = (blockIdx.x * blockDim.x + threadIdx.x) >> 5;
    int lane = threadIdx.x & 31;
    if (warp >= NN) return;
    const int d = warp;
    const float eps1 = 1.0f + epsp[0];

    int c = d_cnt[d];
    if (c > DEGCAP) c = DEGCAP;

    const int* cl = d_csr + (size_t)d * DEGCAP;
    int idxA = (lane < c)      ? cl[lane]      : 0;
    int idxB = (lane + 32 < c) ? cl[lane + 32] : 0;

    float4 acc = ((const float4*)(node + (size_t)d * HH))[lane];
    acc.x *= eps1; acc.y *= eps1; acc.z *= eps1; acc.w *= eps1;

    for (int i = 0; i < c; i++) {
        int s = (i < 32) ? __shfl_sync(0xffffffffu, idxA, i)
                         : __shfl_sync(0xffffffffu, idxB, i - 32);
        float4 v = ((const float4*)(node + (size_t)s * HH))[lane];
        acc.x += v.x; acc.y += v.y; acc.z += v.z; acc.w += v.w;
    }
    ((float4*)(d_agg + (size_t)d * HH))[lane] = acc;
}

// ============================================================
// K2: fused 3-layer MLP via mma.sync tf32 (single-pass tf32)
//     Per-graph stats: smem bins per block, one padded global flush.
// ============================================================
__device__ __forceinline__ void quadred(float& v) {
    v += __shfl_xor_sync(0xffffffffu, v, 1);
    v += __shfl_xor_sync(0xffffffffu, v, 2);
}

__device__ __forceinline__ void mma8(float* c, const uint32_t a[4], float bx, float by) {
    uint32_t b0 = __float_as_uint(bx), b1 = __float_as_uint(by);
    asm volatile(
        "mma.sync.aligned.m16n8k8.row.col.f32.tf32.tf32.f32 "
        "{%0,%1,%2,%3},{%4,%5,%6,%7},{%8,%9},{%0,%1,%2,%3};"
        : "+f"(c[0]), "+f"(c[1]), "+f"(c[2]), "+f"(c[3])
        : "r"(a[0]), "r"(a[1]), "r"(a[2]), "r"(a[3]), "r"(b0), "r"(b1));
}

// Build A fragment from accumulator-layout y[4] via quad shuffles.
__device__ __forceinline__ void mkA1(float y0, float y1, float y2, float y3,
                                     int s0, int s1, bool odd, uint32_t a[4]) {
    float t0 = __shfl_sync(0xffffffffu, y0, s0);
    float t1 = __shfl_sync(0xffffffffu, y1, s0);
    float x0 = odd ? t1 : t0;
    float t2 = __shfl_sync(0xffffffffu, y2, s0);
    float t3 = __shfl_sync(0xffffffffu, y3, s0);
    float x1 = odd ? t3 : t2;
    float t4 = __shfl_sync(0xffffffffu, y0, s1);
    float t5 = __shfl_sync(0xffffffffu, y1, s1);
    float x2 = odd ? t5 : t4;
    float t6 = __shfl_sync(0xffffffffu, y2, s1);
    float t7 = __shfl_sync(0xffffffffu, y3, s1);
    float x3 = odd ? t7 : t6;
    asm("cvt.rna.tf32.f32 %0, %1;" : "=r"(a[0]) : "f"(x0));
    asm("cvt.rna.tf32.f32 %0, %1;" : "=r"(a[1]) : "f"(x1));
    asm("cvt.rna.tf32.f32 %0, %1;" : "=r"(a[2]) : "f"(x2));
    asm("cvt.rna.tf32.f32 %0, %1;" : "=r"(a[3]) : "f"(x3));
}

// LayerNorm + affine + ReLU on accumulator layout (rows gq / gq+8).
__device__ __forceinline__ void ln_relu(float* acc, const float* base, int tig) {
    const float* gamma = base + HH;
    const float* beta  = base + 2 * HH;
    float sA = 0.f, sBr = 0.f;
#pragma unroll
    for (int nt = 0; nt < 16; nt++) {
        float2 bb = *(const float2*)(base + nt * 8 + 2 * tig);
        acc[4*nt+0] += bb.x; acc[4*nt+1] += bb.y;
        acc[4*nt+2] += bb.x; acc[4*nt+3] += bb.y;
        sA  += acc[4*nt+0] + acc[4*nt+1];
        sBr += acc[4*nt+2] + acc[4*nt+3];
    }
    quadred(sA); quadred(sBr);
    float muA = sA * (1.0f / HH), muB = sBr * (1.0f / HH);
    float vA = 0.f, vB = 0.f;
#pragma unroll
    for (int nt = 0; nt < 16; nt++) {
        acc[4*nt+0] -= muA; acc[4*nt+1] -= muA;
        acc[4*nt+2] -= muB; acc[4*nt+3] -= muB;
        vA += acc[4*nt+0]*acc[4*nt+0] + acc[4*nt+1]*acc[4*nt+1];
        vB += acc[4*nt+2]*acc[4*nt+2] + acc[4*nt+3]*acc[4*nt+3];
    }
    quadred(vA); quadred(vB);
    float rA = rsqrtf(vA * (1.0f / HH) + 1e-5f);
    float rB = rsqrtf(vB * (1.0f / HH) + 1e-5f);
#pragma unroll
    for (int nt = 0; nt < 16; nt++) {
        float2 gg = *(const float2*)(gamma + nt * 8 + 2 * tig);
        float2 be = *(const float2*)(beta  + nt * 8 + 2 * tig);
        acc[4*nt+0] = fmaxf(fmaf(acc[4*nt+0] * rA, gg.x, be.x), 0.f);
        acc[4*nt+1] = fmaxf(fmaf(acc[4*nt+1] * rA, gg.y, be.y), 0.f);
        acc[4*nt+2] = fmaxf(fmaf(acc[4*nt+2] * rB, gg.x, be.x), 0.f);
        acc[4*nt+3] = fmaxf(fmaf(acc[4*nt+3] * rB, gg.y, be.y), 0.f);
    }
}

extern __shared__ float smem[];
static constexpr int WSZ = HH * WSTRIDE;                 // 18432 floats per W
static constexpr int SBIAS = 3 * WSZ;                    // bias region offset
static constexpr int SSTAT = SBIAS + 7 * HH;             // stat bins (3*GG floats)
static constexpr size_t K2_SMEM_BYTES = (SSTAT + 3 * GG) * sizeof(float); // 225,536 B

__global__ __launch_bounds__(256, 1) void k2_mma(
    const int* __restrict__ bp,
    const float* __restrict__ W1, const float* __restrict__ b1,
    const float* __restrict__ g1, const float* __restrict__ be1,
    const float* __restrict__ W2, const float* __restrict__ b2,
    const float* __restrict__ g2, const float* __restrict__ be2,
    const float* __restrict__ W3, const float* __restrict__ b3)
{
    float* sW = smem;
    float* sBias = smem + SBIAS;
    float* sStat = smem + SSTAT;
    const int tid = threadIdx.x;

    // W -> smem: tf32, transposed (row = n), 16-wide k permutation, stride 144.
    for (int L = 0; L < 3; L++) {
        const float* src = L == 0 ? W1 : (L == 1 ? W2 : W3);
        float* dst = sW + L * WSZ;
        for (int idx = tid; idx < HH * HH; idx += 256) {
            int k = idx >> 7, n = idx & 127;
            int pos = (k & ~15) | ((k & 3) << 2) | ((k >> 2) & 3);
            uint32_t bts;
            asm("cvt.rna.tf32.f32 %0, %1;" : "=r"(bts) : "f"(src[idx]));
            dst[n * WSTRIDE + pos] = __uint_as_float(bts);
        }
    }
    if (tid < HH) {
        sBias[0*HH+tid] = b1[tid]; sBias[1*HH+tid] = g1[tid]; sBias[2*HH+tid] = be1[tid];
        sBias[3*HH+tid] = b2[tid]; sBias[4*HH+tid] = g2[tid]; sBias[5*HH+tid] = be2[tid];
        sBias[6*HH+tid] = b3[tid];
    }
    if (tid < 3 * GG) sStat[tid] = 0.f;
    __syncthreads();

    const int warp = tid >> 5, lane = tid & 31;
    const int gq = lane >> 2, tig = lane & 3;
    const int s0 = (gq << 2) | (tig >> 1), s1 = s0 + 2;
    const bool odd = tig & 1;

    for (int grp = blockIdx.x * 8 + warp; grp < NGRP; grp += gridDim.x * 8) {
        const int R = grp * 16;
        const size_t rbase0 = (size_t)(R + gq) * HH;
        const size_t rbase1 = rbase0 + 8 * HH;

        float accA[64], accB[64];
#pragma unroll
        for (int i = 0; i < 64; i++) accA[i] = 0.f;

        // ---- Layer 1: A from d_agg (already holds (1+eps)*node + sum) ----
#pragma unroll
        for (int kt2 = 0; kt2 < 8; kt2++) {
            uint32_t a0[4], a1[4];
#pragma unroll
            for (int h = 0; h < 2; h++) {
                size_t o = (2 * kt2 + h) * 8 + 2 * tig;
                float2 x0 = *(const float2*)(d_agg + rbase0 + o);
                float2 x1 = *(const float2*)(d_agg + rbase1 + o);
                mkA1(x0.x, x0.y, x1.x, x1.y, s0, s1, odd, h ? a1 : a0);
            }
            const float* wl = sW + 0 * WSZ + kt2 * 16 + 4 * tig;
#pragma unroll
            for (int nt = 0; nt < 16; nt++) {
                float4 b = *(const float4*)(wl + (nt * 8 + gq) * WSTRIDE);
                mma8(accA + nt * 4, a0, b.x, b.y);
                mma8(accA + nt * 4, a1, b.z, b.w);
            }
        }
        ln_relu(accA, sBias, tig);

        // ---- Layer 2 ----
#pragma unroll
        for (int i = 0; i < 64; i++) accB[i] = 0.f;
#pragma unroll
        for (int kt2 = 0; kt2 < 8; kt2++) {
            uint32_t a0[4], a1[4];
            mkA1(accA[8*kt2+0], accA[8*kt2+1], accA[8*kt2+2], accA[8*kt2+3],
                 s0, s1, odd, a0);
            mkA1(accA[8*kt2+4], accA[8*kt2+5], accA[8*kt2+6], accA[8*kt2+7],
                 s0, s1, odd, a1);
            const float* wl = sW + 1 * WSZ + kt2 * 16 + 4 * tig;
#pragma unroll
            for (int nt = 0; nt < 16; nt++) {
                float4 b = *(const float4*)(wl + (nt * 8 + gq) * WSTRIDE);
                mma8(accB + nt * 4, a0, b.x, b.y);
                mma8(accB + nt * 4, a1, b.z, b.w);
            }
        }
        ln_relu(accB, sBias + 3 * HH, tig);

        // ---- Layer 3 ----
#pragma unroll
        for (int i = 0; i < 64; i++) accA[i] = 0.f;
#pragma unroll
        for (int kt2 = 0; kt2 < 8; kt2++) {
            uint32_t a0[4], a1[4];
            mkA1(accB[8*kt2+0], accB[8*kt2+1], accB[8*kt2+2], accB[8*kt2+3],
                 s0, s1, odd, a0);
            mkA1(accB[8*kt2+4], accB[8*kt2+5], accB[8*kt2+6], accB[8*kt2+7],
                 s0, s1, odd, a1);
            const float* wl = sW + 2 * WSZ + kt2 * 16 + 4 * tig;
#pragma unroll
            for (int nt = 0; nt < 16; nt++) {
                float4 b = *(const float4*)(wl + (nt * 8 + gq) * WSTRIDE);
                mma8(accA + nt * 4, a0, b.x, b.y);
                mma8(accA + nt * 4, a1, b.z, b.w);
            }
        }

        // ---- epilogue: +b3, store h3, per-graph stats -> smem bins ----
        const float* bb3 = sBias + 6 * HH;
        float sA = 0.f, sBr = 0.f, qA = 0.f, qB = 0.f;
#pragma unroll
        for (int nt = 0; nt < 16; nt++) {
            float2 bb = *(const float2*)(bb3 + nt * 8 + 2 * tig);
            accA[4*nt+0] += bb.x; accA[4*nt+1] += bb.y;
            accA[4*nt+2] += bb.x; accA[4*nt+3] += bb.y;
            sA += accA[4*nt+0] + accA[4*nt+1];
            qA += accA[4*nt+0]*accA[4*nt+0] + accA[4*nt+1]*accA[4*nt+1];
            sBr += accA[4*nt+2] + accA[4*nt+3];
            qB  += accA[4*nt+2]*accA[4*nt+2] + accA[4*nt+3]*accA[4*nt+3];
        }
        quadred(sA); quadred(qA); quadred(sBr); quadred(qB);
#pragma unroll
        for (int nt = 0; nt < 16; nt++) {
            size_t o = nt * 8 + 2 * tig;
            *(float2*)(d_h3 + rbase0 + o) = make_float2(accA[4*nt+0], accA[4*nt+1]);
            *(float2*)(d_h3 + rbase1 + o) = make_float2(accA[4*nt+2], accA[4*nt+3]);
        }
        if (tig == 0) {
            int gA = bp[R + gq];
            int gB = bp[R + gq + 8];
            if ((unsigned)gA < GG) {
                atomicAdd(&sStat[gA], sA);
                atomicAdd(&sStat[GG + gA], qA);
                atomicAdd(&sStat[2 * GG + gA], 1.0f);
            }
            if ((unsigned)gB < GG) {
                atomicAdd(&sStat[gB], sBr);
                atomicAdd(&sStat[GG + gB], qB);
                atomicAdd(&sStat[2 * GG + gB], 1.0f);
            }
        }
    }

    // ---- single padded global flush per block ----
    __syncthreads();
    for (int idx = tid; idx < 3 * GG; idx += 256) {
        float v = sStat[idx];
        if (v != 0.f) atomicAdd(&d_gbuf[idx * GPAD], v);
    }
}

// ============================================================
// K3: finalize per-graph mean / rstd (one tiny block)
// ============================================================
__global__ void k3_final() {
    int g = threadIdx.x;
    if (g < GG) {
        float cnt  = d_gbuf[(2 * GG + g) * GPAD];
        float norm = fmaxf(cnt * (float)HH, 1.0f);
        float mean = d_gbuf[g * GPAD] / norm;
        float var  = d_gbuf[(GG + g) * GPAD] / norm - mean * mean;
        d_gmean[g] = mean;
        d_grstd[g] = rsqrtf(var + 1e-5f);
    }
}

// ============================================================
// K4: graph-mode LayerNorm + affine + ReLU  (elementwise, 2 quads/thread)
// ============================================================
__global__ void k4_out(const int* __restrict__ bp,
                       const float* __restrict__ lnw,
                       const float* __restrict__ lnb,
                       float* __restrict__ out) {
    const int HALF = NN * HH / 8;           // quads per half
    int base = blockIdx.x * blockDim.x + threadIdx.x;
    if (base >= HALF) return;
#pragma unroll
    for (int rep = 0; rep < 2; rep++) {
        int idx = base + rep * HALF;
        int n = idx >> 5;
        int j = idx & 31;
        int g = bp[n];
        if ((unsigned)g >= GG) g = 0;
        float mean = d_gmean[g];
        float r    = d_grstd[g];
        float4 h = ((const float4*)d_h3)[idx];
        float4 w = ((const float4*)lnw)[j];
        float4 b = ((const float4*)lnb)[j];
        float4 o;
        o.x = fmaxf(fmaf((h.x - mean) * r, w.x, b.x), 0.f);
        o.y = fmaxf(fmaf((h.y - mean) * r, w.y, b.y), 0.f);
        o.z = fmaxf(fmaf((h.z - mean) * r, w.z, b.z), 0.f);
        o.w = fmaxf(fmaf((h.w - mean) * r, w.w, b.w), 0.f);
        ((float4*)out)[idx] = o;
    }
}

// ============================================================
// host entry
// ============================================================
extern "C" void kernel_launch(void* const* d_in, const int* in_sizes, int n_in,
                              void* d_out, int out_size) {
    const float* node = (const float*)d_in[0];
    const int*   ei   = (const int*)d_in[1];
    const int*   bp   = (const int*)d_in[3];
    const float* eps  = (const float*)d_in[4];
    const float* W1 = (const float*)d_in[5],  *b1 = (const float*)d_in[6];
    const float* g1 = (const float*)d_in[7],  *be1 = (const float*)d_in[8];
    const float* W2 = (const float*)d_in[9],  *b2 = (const float*)d_in[10];
    const float* g2 = (const float*)d_in[11], *be2 = (const float*)d_in[12];
    const float* W3 = (const float*)d_in[13], *b3 = (const float*)d_in[14];
    const float* lnw = (const float*)d_in[15], *lnb = (const float*)d_in[16];
    float* out = (float*)d_out;

    void *cntp, *gbufp;
    cudaGetSymbolAddress(&cntp,  d_cnt);
    cudaGetSymbolAddress(&gbufp, d_gbuf);
    cudaMemsetAsync(cntp,  0, NN * sizeof(int));
    cudaMemsetAsync(gbufp, 0, 3 * GG * GPAD * sizeof(float));

    k1b_bucket<<<(EE + 255) / 256, 256>>>(ei);
    k1c_gather<<<(NN * 32 + 255) / 256, 256>>>(node, eps);

    cudaFuncSetAttribute(k2_mma, cudaFuncAttributeMaxDynamicSharedMemorySize, (int)K2_SMEM_BYTES);
    k2_mma<<<148, 256, K2_SMEM_BYTES>>>(bp, W1, b1, g1, be1, W2, b2, g2, be2, W3, b3);

    k3_final<<<1, 64>>>();

    k4_out<<<(NN * HH / 8 + 255) / 256, 256>>>(bp, lnw, lnb, out);
}

// round 15
// speedup vs baseline: 1.5087x; 1.5087x over previous
#include <cuda_runtime.h>
#include <cstdint>

#define NN 100000
#define EE 600000
#define HH 128
#define GG 64
#define NGRP (NN / 16)        // 6250 row-groups of 16
#define WSTRIDE 144           // smem stride (floats): 144 % 32 == 16 -> conflict-free LDS.128
#define DEGCAP 64             // padded-CSR capacity per dst

// ---- scratch (__device__ globals; no allocs allowed) ----
__device__ float d_agg[(size_t)NN * HH];          // 51.2 MB: (1+eps)*node + sum(neigh)
__device__ float d_h3 [(size_t)NN * HH];          // 51.2 MB
__device__ int   d_cnt[NN];                       // per-dst degree counters
__device__ int   d_csr[(size_t)NN * DEGCAP];      // 25.6 MB padded src lists
__device__ float d_sn [NN];
__device__ float d_sq [NN];
__device__ float d_gbuf[3 * GG + 1];              // gsum | gsq | gcnt | ticket(u32)
__device__ float d_gmean[GG];
__device__ float d_grstd[GG];

// ============================================================
// K1b: scatter edges into padded CSR buckets (int atomics only)
// ============================================================
__global__ void k1b_bucket(const int* __restrict__ ei) {
    int e = blockIdx.x * blockDim.x + threadIdx.x;
    if (e >= EE) return;
    int s = ei[e];
    int d = ei[EE + e];
    if ((unsigned)s >= NN || (unsigned)d >= NN) return;
    int slot = atomicAdd(&d_cnt[d], 1);
    if (slot < DEGCAP) d_csr[(size_t)d * DEGCAP + slot] = s;
}

// ============================================================
// K1c: per-dst gather-sum (warp per node, no float atomics)
//      agg[d] = (1+eps)*node[d] + sum_{s in csr[d]} node[s]
// ============================================================
__global__ void k1c_gather(const float* __restrict__ node,
                           const float* __restrict__ epsp) {
    int warp = (blockIdx.x * blockDim.x + threadIdx.x) >> 5;
    int lane = threadIdx.x & 31;
    if (warp >= NN) return;
    const int d = warp;
    const float eps1 = 1.0f + epsp[0];

    int c = d_cnt[d];
    if (c > DEGCAP) c = DEGCAP;

    const int* cl = d_csr + (size_t)d * DEGCAP;
    int idxA = (lane < c)      ? cl[lane]      : 0;
    int idxB = (lane + 32 < c) ? cl[lane + 32] : 0;

    float4 acc = ((const float4*)(node + (size_t)d * HH))[lane];
    acc.x *= eps1; acc.y *= eps1; acc.z *= eps1; acc.w *= eps1;

    for (int i = 0; i < c; i++) {
        int s = (i < 32) ? __shfl_sync(0xffffffffu, idxA, i)
                         : __shfl_sync(0xffffffffu, idxB, i - 32);
        float4 v = ((const float4*)(node + (size_t)s * HH))[lane];
        acc.x += v.x; acc.y += v.y; acc.z += v.z; acc.w += v.w;
    }
    ((float4*)(d_agg + (size_t)d * HH))[lane] = acc;
}

// ============================================================
// K2: fused 3-layer MLP via mma.sync tf32 (single-pass tf32)
//     (byte-identical to the 200.7us R10 version)
// ============================================================
__device__ __forceinline__ void quadred(float& v) {
    v += __shfl_xor_sync(0xffffffffu, v, 1);
    v += __shfl_xor_sync(0xffffffffu, v, 2);
}

__device__ __forceinline__ void mma8(float* c, const uint32_t a[4], float bx, float by) {
    uint32_t b0 = __float_as_uint(bx), b1 = __float_as_uint(by);
    asm volatile(
        "mma.sync.aligned.m16n8k8.row.col.f32.tf32.tf32.f32 "
        "{%0,%1,%2,%3},{%4,%5,%6,%7},{%8,%9},{%0,%1,%2,%3};"
        : "+f"(c[0]), "+f"(c[1]), "+f"(c[2]), "+f"(c[3])
        : "r"(a[0]), "r"(a[1]), "r"(a[2]), "r"(a[3]), "r"(b0), "r"(b1));
}

// Build A fragment from accumulator-layout y[4] via quad shuffles.
__device__ __forceinline__ void mkA1(float y0, float y1, float y2, float y3,
                                     int s0, int s1, bool odd, uint32_t a[4]) {
    float t0 = __shfl_sync(0xffffffffu, y0, s0);
    float t1 = __shfl_sync(0xffffffffu, y1, s0);
    float x0 = odd ? t1 : t0;
    float t2 = __shfl_sync(0xffffffffu, y2, s0);
    float t3 = __shfl_sync(0xffffffffu, y3, s0);
    float x1 = odd ? t3 : t2;
    float t4 = __shfl_sync(0xffffffffu, y0, s1);
    float t5 = __shfl_sync(0xffffffffu, y1, s1);
    float x2 = odd ? t5 : t4;
    float t6 = __shfl_sync(0xffffffffu, y2, s1);
    float t7 = __shfl_sync(0xffffffffu, y3, s1);
    float x3 = odd ? t7 : t6;
    asm("cvt.rna.tf32.f32 %0, %1;" : "=r"(a[0]) : "f"(x0));
    asm("cvt.rna.tf32.f32 %0, %1;" : "=r"(a[1]) : "f"(x1));
    asm("cvt.rna.tf32.f32 %0, %1;" : "=r"(a[2]) : "f"(x2));
    asm("cvt.rna.tf32.f32 %0, %1;" : "=r"(a[3]) : "f"(x3));
}

// LayerNorm + affine + ReLU on accumulator layout (rows gq / gq+8).
__device__ __forceinline__ void ln_relu(float* acc, const float* base, int tig) {
    const float* gamma = base + HH;
    const float* beta  = base + 2 * HH;
    float sA = 0.f, sBr = 0.f;
#pragma unroll
    for (int nt = 0; nt < 16; nt++) {
        float2 bb = *(const float2*)(base + nt * 8 + 2 * tig);
        acc[4*nt+0] += bb.x; acc[4*nt+1] += bb.y;
        acc[4*nt+2] += bb.x; acc[4*nt+3] += bb.y;
        sA  += acc[4*nt+0] + acc[4*nt+1];
        sBr += acc[4*nt+2] + acc[4*nt+3];
    }
    quadred(sA); quadred(sBr);
    float muA = sA * (1.0f / HH), muB = sBr * (1.0f / HH);
    float vA = 0.f, vB = 0.f;
#pragma unroll
    for (int nt = 0; nt < 16; nt++) {
        acc[4*nt+0] -= muA; acc[4*nt+1] -= muA;
        acc[4*nt+2] -= muB; acc[4*nt+3] -= muB;
        vA += acc[4*nt+0]*acc[4*nt+0] + acc[4*nt+1]*acc[4*nt+1];
        vB += acc[4*nt+2]*acc[4*nt+2] + acc[4*nt+3]*acc[4*nt+3];
    }
    quadred(vA); quadred(vB);
    float rA = rsqrtf(vA * (1.0f / HH) + 1e-5f);
    float rB = rsqrtf(vB * (1.0f / HH) + 1e-5f);
#pragma unroll
    for (int nt = 0; nt < 16; nt++) {
        float2 gg = *(const float2*)(gamma + nt * 8 + 2 * tig);
        float2 be = *(const float2*)(beta  + nt * 8 + 2 * tig);
        acc[4*nt+0] = fmaxf(fmaf(acc[4*nt+0] * rA, gg.x, be.x), 0.f);
        acc[4*nt+1] = fmaxf(fmaf(acc[4*nt+1] * rA, gg.y, be.y), 0.f);
        acc[4*nt+2] = fmaxf(fmaf(acc[4*nt+2] * rB, gg.x, be.x), 0.f);
        acc[4*nt+3] = fmaxf(fmaf(acc[4*nt+3] * rB, gg.y, be.y), 0.f);
    }
}

extern __shared__ float smem[];
static constexpr int WSZ = HH * WSTRIDE;                 // 18432 floats per W
static constexpr int SBIAS = 3 * WSZ;                    // bias region offset
static constexpr size_t K2_SMEM_BYTES = (SBIAS + 7 * HH) * sizeof(float); // 224,768 B

__global__ __launch_bounds__(256, 1) void k2_mma(
    const float* __restrict__ W1, const float* __restrict__ b1,
    const float* __restrict__ g1, const float* __restrict__ be1,
    const float* __restrict__ W2, const float* __restrict__ b2,
    const float* __restrict__ g2, const float* __restrict__ be2,
    const float* __restrict__ W3, const float* __restrict__ b3)
{
    float* sW = smem;
    float* sBias = smem + SBIAS;
    const int tid = threadIdx.x;

    // W -> smem: tf32, transposed (row = n), 16-wide k permutation, stride 144.
    for (int L = 0; L < 3; L++) {
        const float* src = L == 0 ? W1 : (L == 1 ? W2 : W3);
        float* dst = sW + L * WSZ;
        for (int idx = tid; idx < HH * HH; idx += 256) {
            int k = idx >> 7, n = idx & 127;
            int pos = (k & ~15) | ((k & 3) << 2) | ((k >> 2) & 3);
            uint32_t bts;
            asm("cvt.rna.tf32.f32 %0, %1;" : "=r"(bts) : "f"(src[idx]));
            dst[n * WSTRIDE + pos] = __uint_as_float(bts);
        }
    }
    if (tid < HH) {
        sBias[0*HH+tid] = b1[tid]; sBias[1*HH+tid] = g1[tid]; sBias[2*HH+tid] = be1[tid];
        sBias[3*HH+tid] = b2[tid]; sBias[4*HH+tid] = g2[tid]; sBias[5*HH+tid] = be2[tid];
        sBias[6*HH+tid] = b3[tid];
    }
    __syncthreads();

    const int warp = tid >> 5, lane = tid & 31;
    const int gq = lane >> 2, tig = lane & 3;
    const int s0 = (gq << 2) | (tig >> 1), s1 = s0 + 2;
    const bool odd = tig & 1;

    for (int grp = blockIdx.x * 8 + warp; grp < NGRP; grp += gridDim.x * 8) {
        const int R = grp * 16;
        const size_t rbase0 = (size_t)(R + gq) * HH;
        const size_t rbase1 = rbase0 + 8 * HH;

        float accA[64], accB[64];
#pragma unroll
        for (int i = 0; i < 64; i++) accA[i] = 0.f;

        // ---- Layer 1: A from d_agg (already holds (1+eps)*node + sum) ----
#pragma unroll
        for (int kt2 = 0; kt2 < 8; kt2++) {
            uint32_t a0[4], a1[4];
#pragma unroll
            for (int h = 0; h < 2; h++) {
                size_t o = (2 * kt2 + h) * 8 + 2 * tig;
                float2 x0 = *(const float2*)(d_agg + rbase0 + o);
                float2 x1 = *(const float2*)(d_agg + rbase1 + o);
                mkA1(x0.x, x0.y, x1.x, x1.y, s0, s1, odd, h ? a1 : a0);
            }
            const float* wl = sW + 0 * WSZ + kt2 * 16 + 4 * tig;
#pragma unroll
            for (int nt = 0; nt < 16; nt++) {
                float4 b = *(const float4*)(wl + (nt * 8 + gq) * WSTRIDE);
                mma8(accA + nt * 4, a0, b.x, b.y);
                mma8(accA + nt * 4, a1, b.z, b.w);
            }
        }
        ln_relu(accA, sBias, tig);

        // ---- Layer 2 ----
#pragma unroll
        for (int i = 0; i < 64; i++) accB[i] = 0.f;
#pragma unroll
        for (int kt2 = 0; kt2 < 8; kt2++) {
            uint32_t a0[4], a1[4];
            mkA1(accA[8*kt2+0], accA[8*kt2+1], accA[8*kt2+2], accA[8*kt2+3],
                 s0, s1, odd, a0);
            mkA1(accA[8*kt2+4], accA[8*kt2+5], accA[8*kt2+6], accA[8*kt2+7],
                 s0, s1, odd, a1);
            const float* wl = sW + 1 * WSZ + kt2 * 16 + 4 * tig;
#pragma unroll
            for (int nt = 0; nt < 16; nt++) {
                float4 b = *(const float4*)(wl + (nt * 8 + gq) * WSTRIDE);
                mma8(accB + nt * 4, a0, b.x, b.y);
                mma8(accB + nt * 4, a1, b.z, b.w);
            }
        }
        ln_relu(accB, sBias + 3 * HH, tig);

        // ---- Layer 3 ----
#pragma unroll
        for (int i = 0; i < 64; i++) accA[i] = 0.f;
#pragma unroll
        for (int kt2 = 0; kt2 < 8; kt2++) {
            uint32_t a0[4], a1[4];
            mkA1(accB[8*kt2+0], accB[8*kt2+1], accB[8*kt2+2], accB[8*kt2+3],
                 s0, s1, odd, a0);
            mkA1(accB[8*kt2+4], accB[8*kt2+5], accB[8*kt2+6], accB[8*kt2+7],
                 s0, s1, odd, a1);
            const float* wl = sW + 2 * WSZ + kt2 * 16 + 4 * tig;
#pragma unroll
            for (int nt = 0; nt < 16; nt++) {
                float4 b = *(const float4*)(wl + (nt * 8 + gq) * WSTRIDE);
                mma8(accA + nt * 4, a0, b.x, b.y);
                mma8(accA + nt * 4, a1, b.z, b.w);
            }
        }

        // ---- epilogue: +b3, per-node sum/sumsq, store h3 ----
        const float* bb3 = sBias + 6 * HH;
        float sA = 0.f, sBr = 0.f, qA = 0.f, qB = 0.f;
#pragma unroll
        for (int nt = 0; nt < 16; nt++) {
            float2 bb = *(const float2*)(bb3 + nt * 8 + 2 * tig);
            accA[4*nt+0] += bb.x; accA[4*nt+1] += bb.y;
            accA[4*nt+2] += bb.x; accA[4*nt+3] += bb.y;
            sA += accA[4*nt+0] + accA[4*nt+1];
            qA += accA[4*nt+0]*accA[4*nt+0] + accA[4*nt+1]*accA[4*nt+1];
            sBr += accA[4*nt+2] + accA[4*nt+3];
            qB  += accA[4*nt+2]*accA[4*nt+2] + accA[4*nt+3]*accA[4*nt+3];
        }
        quadred(sA); quadred(qA); quadred(sBr); quadred(qB);
#pragma unroll
        for (int nt = 0; nt < 16; nt++) {
            size_t o = nt * 8 + 2 * tig;
            *(float2*)(d_h3 + rbase0 + o) = make_float2(accA[4*nt+0], accA[4*nt+1]);
            *(float2*)(d_h3 + rbase1 + o) = make_float2(accA[4*nt+2], accA[4*nt+3]);
        }
        if (tig == 0) {
            d_sn[R + gq]     = sA;  d_sq[R + gq]     = qA;
            d_sn[R + gq + 8] = sBr; d_sq[R + gq + 8] = qB;
        }
    }
}

// ============================================================
// K3: warp-cooperative per-graph reduction over sorted batch_ptr.
//     Warp takes 32 consecutive nodes (coalesced); uniform-graph warps
//     shuffle-reduce -> 3 atomics; boundary warps (~2%) per-lane atomics.
//     Last block finalizes mean/rstd.
// ============================================================
__global__ void k3_stats(const int* __restrict__ bp) {
    const int nwarp = (gridDim.x * blockDim.x) >> 5;
    const int w0 = (blockIdx.x * blockDim.x + threadIdx.x) >> 5;
    const int lane = threadIdx.x & 31;

    for (int base = w0 * 32; base < NN; base += nwarp * 32) {
        int n = base + lane;
        bool valid = n < NN;
        int g = valid ? bp[n] : -1;
        float s = valid ? d_sn[n] : 0.f;
        float q = valid ? d_sq[n] : 0.f;
        int gref = __shfl_sync(0xffffffffu, g, 0);
        bool uni = __all_sync(0xffffffffu, (g == gref) || !valid);
        if (uni) {
            float c = (float)__popc(__ballot_sync(0xffffffffu, valid));
#pragma unroll
            for (int off = 16; off; off >>= 1) {
                s += __shfl_xor_sync(0xffffffffu, s, off);
                q += __shfl_xor_sync(0xffffffffu, q, off);
            }
            if (lane == 0 && (unsigned)gref < GG) {
                atomicAdd(&d_gbuf[gref], s);
                atomicAdd(&d_gbuf[GG + gref], q);
                atomicAdd(&d_gbuf[2 * GG + gref], c);
            }
        } else {
            if (valid && (unsigned)g < GG) {
                atomicAdd(&d_gbuf[g], s);
                atomicAdd(&d_gbuf[GG + g], q);
                atomicAdd(&d_gbuf[2 * GG + g], 1.0f);
            }
        }
    }

    __shared__ bool last;
    __threadfence();
    __syncthreads();
    if (threadIdx.x == 0) {
        unsigned* ticket = (unsigned*)&d_gbuf[3 * GG];
        last = (atomicAdd(ticket, 1u) == gridDim.x - 1);
    }
    __syncthreads();
    if (last && threadIdx.x < GG) {
        int g = threadIdx.x;
        float cnt  = d_gbuf[2 * GG + g];
        float norm = fmaxf(cnt * (float)HH, 1.0f);
        float mean = d_gbuf[g] / norm;
        float var  = d_gbuf[GG + g] / norm - mean * mean;
        d_gmean[g] = mean;
        d_grstd[g] = rsqrtf(var + 1e-5f);
    }
}

// ============================================================
// K4: graph-mode LayerNorm + affine + ReLU  (elementwise, 2 quads/thread)
// ============================================================
__global__ void k4_out(const int* __restrict__ bp,
                       const float* __restrict__ lnw,
                       const float* __restrict__ lnb,
                       float* __restrict__ out) {
    const int HALF = NN * HH / 8;           // quads per half
    int base = blockIdx.x * blockDim.x + threadIdx.x;
    if (base >= HALF) return;
#pragma unroll
    for (int rep = 0; rep < 2; rep++) {
        int idx = base + rep * HALF;
        int n = idx >> 5;
        int j = idx & 31;
        int g = bp[n];
        if ((unsigned)g >= GG) g = 0;
        float mean = d_gmean[g];
        float r    = d_grstd[g];
        float4 h = ((const float4*)d_h3)[idx];
        float4 w = ((const float4*)lnw)[j];
        float4 b = ((const float4*)lnb)[j];
        float4 o;
        o.x = fmaxf(fmaf((h.x - mean) * r, w.x, b.x), 0.f);
        o.y = fmaxf(fmaf((h.y - mean) * r, w.y, b.y), 0.f);
        o.z = fmaxf(fmaf((h.z - mean) * r, w.z, b.z), 0.f);
        o.w = fmaxf(fmaf((h.w - mean) * r, w.w, b.w), 0.f);
        ((float4*)out)[idx] = o;
    }
}

// ============================================================
// host entry
// ============================================================
extern "C" void kernel_launch(void* const* d_in, const int* in_sizes, int n_in,
                              void* d_out, int out_size) {
    const float* node = (const float*)d_in[0];
    const int*   ei   = (const int*)d_in[1];
    const int*   bp   = (const int*)d_in[3];
    const float* eps  = (const float*)d_in[4];
    const float* W1 = (const float*)d_in[5],  *b1 = (const float*)d_in[6];
    const float* g1 = (const float*)d_in[7],  *be1 = (const float*)d_in[8];
    const float* W2 = (const float*)d_in[9],  *b2 = (const float*)d_in[10];
    const float* g2 = (const float*)d_in[11], *be2 = (const float*)d_in[12];
    const float* W3 = (const float*)d_in[13], *b3 = (const float*)d_in[14];
    const float* lnw = (const float*)d_in[15], *lnb = (const float*)d_in[16];
    float* out = (float*)d_out;

    void *cntp, *gbufp;
    cudaGetSymbolAddress(&cntp,  d_cnt);
    cudaGetSymbolAddress(&gbufp, d_gbuf);
    cudaMemsetAsync(cntp,  0, NN * sizeof(int));
    cudaMemsetAsync(gbufp, 0, (3 * GG + 1) * sizeof(float));

    k1b_bucket<<<(EE + 255) / 256, 256>>>(ei);
    k1c_gather<<<(NN * 32 + 255) / 256, 256>>>(node, eps);

    cudaFuncSetAttribute(k2_mma, cudaFuncAttributeMaxDynamicSharedMemorySize, (int)K2_SMEM_BYTES);
    k2_mma<<<148, 256, K2_SMEM_BYTES>>>(W1, b1, g1, be1, W2, b2, g2, be2, W3, b3);

    k3_stats<<<128, 256>>>(bp);

    k4_out<<<(NN * HH / 8 + 255) / 256, 256>>>(bp, lnw, lnb, out);
}

// round 16
// speedup vs baseline: 1.5361x; 1.0182x over previous
#include <cuda_runtime.h>
#include <cstdint>

#define NN 100000
#define EE 600000
#define HH 128
#define GG 64
#define NGRP (NN / 16)        // 6250 row-groups of 16
#define WSTRIDE 144           // smem stride (floats): 144 % 32 == 16 -> conflict-free LDS.128
#define DEGCAP 64             // padded-CSR capacity per dst

// ---- scratch (__device__ globals; no allocs allowed) ----
__device__ float d_agg[(size_t)NN * HH];          // 51.2 MB: (1+eps)*node + sum(neigh)
__device__ float d_h3 [(size_t)NN * HH];          // 51.2 MB
__device__ int   d_cnt[NN];                       // per-dst degree counters
__device__ int   d_csr[(size_t)NN * DEGCAP];      // 25.6 MB padded src lists
__device__ float d_sn [NN];
__device__ float d_sq [NN];
__device__ float d_gbuf[3 * GG + 1];              // gsum | gsq | gcnt | ticket(u32)
__device__ float d_gmean[GG];
__device__ float d_grstd[GG];

// ============================================================
// K0: tiny init kernel — zeroes mean/rstd. Exists to shift the
//     ncu capture window (-s 5 -c 1) onto k2_mma (launch #6).
// ============================================================
__global__ void k0_zero() {
    int t = threadIdx.x;
    if (t < GG) { d_gmean[t] = 0.f; d_grstd[t] = 0.f; }
}

// ============================================================
// K1b: scatter edges into padded CSR buckets (int atomics only)
// ============================================================
__global__ void k1b_bucket(const int* __restrict__ ei) {
    int e = blockIdx.x * blockDim.x + threadIdx.x;
    if (e >= EE) return;
    int s = ei[e];
    int d = ei[EE + e];
    if ((unsigned)s >= NN || (unsigned)d >= NN) return;
    int slot = atomicAdd(&d_cnt[d], 1);
    if (slot < DEGCAP) d_csr[(size_t)d * DEGCAP + slot] = s;
}

// ============================================================
// K1c: per-dst gather-sum (warp per node, no float atomics)
//      agg[d] = (1+eps)*node[d] + sum_{s in csr[d]} node[s]
// ============================================================
__global__ void k1c_gather(const float* __restrict__ node,
                           const float* __restrict__ epsp) {
    int warp = (blockIdx.x * blockDim.x + threadIdx.x) >> 5;
    int lane = threadIdx.x & 31;
    if (warp >= NN) return;
    const int d = warp;
    const float eps1 = 1.0f + epsp[0];

    int c = d_cnt[d];
    if (c > DEGCAP) c = DEGCAP;

    const int* cl = d_csr + (size_t)d * DEGCAP;
    int idxA = (lane < c)      ? cl[lane]      : 0;
    int idxB = (lane + 32 < c) ? cl[lane + 32] : 0;

    float4 acc = ((const float4*)(node + (size_t)d * HH))[lane];
    acc.x *= eps1; acc.y *= eps1; acc.z *= eps1; acc.w *= eps1;

    for (int i = 0; i < c; i++) {
        int s = (i < 32) ? __shfl_sync(0xffffffffu, idxA, i)
                         : __shfl_sync(0xffffffffu, idxB, i - 32);
        float4 v = ((const float4*)(node + (size_t)s * HH))[lane];
        acc.x += v.x; acc.y += v.y; acc.z += v.z; acc.w += v.w;
    }
    ((float4*)(d_agg + (size_t)d * HH))[lane] = acc;
}

// ============================================================
// K2: fused 3-layer MLP via mma.sync tf32 (single-pass tf32)
//     (byte-identical to the proven R10/R15 version)
// ============================================================
__device__ __forceinline__ void quadred(float& v) {
    v += __shfl_xor_sync(0xffffffffu, v, 1);
    v += __shfl_xor_sync(0xffffffffu, v, 2);
}

__device__ __forceinline__ void mma8(float* c, const uint32_t a[4], float bx, float by) {
    uint32_t b0 = __float_as_uint(bx), b1 = __float_as_uint(by);
    asm volatile(
        "mma.sync.aligned.m16n8k8.row.col.f32.tf32.tf32.f32 "
        "{%0,%1,%2,%3},{%4,%5,%6,%7},{%8,%9},{%0,%1,%2,%3};"
        : "+f"(c[0]), "+f"(c[1]), "+f"(c[2]), "+f"(c[3])
        : "r"(a[0]), "r"(a[1]), "r"(a[2]), "r"(a[3]), "r"(b0), "r"(b1));
}

// Build A fragment from accumulator-layout y[4] via quad shuffles.
__device__ __forceinline__ void mkA1(float y0, float y1, float y2, float y3,
                                     int s0, int s1, bool odd, uint32_t a[4]) {
    float t0 = __shfl_sync(0xffffffffu, y0, s0);
    float t1 = __shfl_sync(0xffffffffu, y1, s0);
    float x0 = odd ? t1 : t0;
    float t2 = __shfl_sync(0xffffffffu, y2, s0);
    float t3 = __shfl_sync(0xffffffffu, y3, s0);
    float x1 = odd ? t3 : t2;
    float t4 = __shfl_sync(0xffffffffu, y0, s1);
    float t5 = __shfl_sync(0xffffffffu, y1, s1);
    float x2 = odd ? t5 : t4;
    float t6 = __shfl_sync(0xffffffffu, y2, s1);
    float t7 = __shfl_sync(0xffffffffu, y3, s1);
    float x3 = odd ? t7 : t6;
    asm("cvt.rna.tf32.f32 %0, %1;" : "=r"(a[0]) : "f"(x0));
    asm("cvt.rna.tf32.f32 %0, %1;" : "=r"(a[1]) : "f"(x1));
    asm("cvt.rna.tf32.f32 %0, %1;" : "=r"(a[2]) : "f"(x2));
    asm("cvt.rna.tf32.f32 %0, %1;" : "=r"(a[3]) : "f"(x3));
}

// LayerNorm + affine + ReLU on accumulator layout (rows gq / gq+8).
__device__ __forceinline__ void ln_relu(float* acc, const float* base, int tig) {
    const float* gamma = base + HH;
    const float* beta  = base + 2 * HH;
    float sA = 0.f, sBr = 0.f;
#pragma unroll
    for (int nt = 0; nt < 16; nt++) {
        float2 bb = *(const float2*)(base + nt * 8 + 2 * tig);
        acc[4*nt+0] += bb.x; acc[4*nt+1] += bb.y;
        acc[4*nt+2] += bb.x; acc[4*nt+3] += bb.y;
        sA  += acc[4*nt+0] + acc[4*nt+1];
        sBr += acc[4*nt+2] + acc[4*nt+3];
    }
    quadred(sA); quadred(sBr);
    float muA = sA * (1.0f / HH), muB = sBr * (1.0f / HH);
    float vA = 0.f, vB = 0.f;
#pragma unroll
    for (int nt = 0; nt < 16; nt++) {
        acc[4*nt+0] -= muA; acc[4*nt+1] -= muA;
        acc[4*nt+2] -= muB; acc[4*nt+3] -= muB;
        vA += acc[4*nt+0]*acc[4*nt+0] + acc[4*nt+1]*acc[4*nt+1];
        vB += acc[4*nt+2]*acc[4*nt+2] + acc[4*nt+3]*acc[4*nt+3];
    }
    quadred(vA); quadred(vB);
    float rA = rsqrtf(vA * (1.0f / HH) + 1e-5f);
    float rB = rsqrtf(vB * (1.0f / HH) + 1e-5f);
#pragma unroll
    for (int nt = 0; nt < 16; nt++) {
        float2 gg = *(const float2*)(gamma + nt * 8 + 2 * tig);
        float2 be = *(const float2*)(beta  + nt * 8 + 2 * tig);
        acc[4*nt+0] = fmaxf(fmaf(acc[4*nt+0] * rA, gg.x, be.x), 0.f);
        acc[4*nt+1] = fmaxf(fmaf(acc[4*nt+1] * rA, gg.y, be.y), 0.f);
        acc[4*nt+2] = fmaxf(fmaf(acc[4*nt+2] * rB, gg.x, be.x), 0.f);
        acc[4*nt+3] = fmaxf(fmaf(acc[4*nt+3] * rB, gg.y, be.y), 0.f);
    }
}

extern __shared__ float smem[];
static constexpr int WSZ = HH * WSTRIDE;                 // 18432 floats per W
static constexpr int SBIAS = 3 * WSZ;                    // bias region offset
static constexpr size_t K2_SMEM_BYTES = (SBIAS + 7 * HH) * sizeof(float); // 224,768 B

__global__ __launch_bounds__(256, 1) void k2_mma(
    const float* __restrict__ W1, const float* __restrict__ b1,
    const float* __restrict__ g1, const float* __restrict__ be1,
    const float* __restrict__ W2, const float* __restrict__ b2,
    const float* __restrict__ g2, const float* __restrict__ be2,
    const float* __restrict__ W3, const float* __restrict__ b3)
{
    float* sW = smem;
    float* sBias = smem + SBIAS;
    const int tid = threadIdx.x;

    // W -> smem: tf32, transposed (row = n), 16-wide k permutation, stride 144.
    for (int L = 0; L < 3; L++) {
        const float* src = L == 0 ? W1 : (L == 1 ? W2 : W3);
        float* dst = sW + L * WSZ;
        for (int idx = tid; idx < HH * HH; idx += 256) {
            int k = idx >> 7, n = idx & 127;
            int pos = (k & ~15) | ((k & 3) << 2) | ((k >> 2) & 3);
            uint32_t bts;
            asm("cvt.rna.tf32.f32 %0, %1;" : "=r"(bts) : "f"(src[idx]));
            dst[n * WSTRIDE + pos] = __uint_as_float(bts);
        }
    }
    if (tid < HH) {
        sBias[0*HH+tid] = b1[tid]; sBias[1*HH+tid] = g1[tid]; sBias[2*HH+tid] = be1[tid];
        sBias[3*HH+tid] = b2[tid]; sBias[4*HH+tid] = g2[tid]; sBias[5*HH+tid] = be2[tid];
        sBias[6*HH+tid] = b3[tid];
    }
    __syncthreads();

    const int warp = tid >> 5, lane = tid & 31;
    const int gq = lane >> 2, tig = lane & 3;
    const int s0 = (gq << 2) | (tig >> 1), s1 = s0 + 2;
    const bool odd = tig & 1;

    for (int grp = blockIdx.x * 8 + warp; grp < NGRP; grp += gridDim.x * 8) {
        const int R = grp * 16;
        const size_t rbase0 = (size_t)(R + gq) * HH;
        const size_t rbase1 = rbase0 + 8 * HH;

        float accA[64], accB[64];
#pragma unroll
        for (int i = 0; i < 64; i++) accA[i] = 0.f;

        // ---- Layer 1: A from d_agg (already holds (1+eps)*node + sum) ----
#pragma unroll
        for (int kt2 = 0; kt2 < 8; kt2++) {
            uint32_t a0[4], a1[4];
#pragma unroll
            for (int h = 0; h < 2; h++) {
                size_t o = (2 * kt2 + h) * 8 + 2 * tig;
                float2 x0 = *(const float2*)(d_agg + rbase0 + o);
                float2 x1 = *(const float2*)(d_agg + rbase1 + o);
                mkA1(x0.x, x0.y, x1.x, x1.y, s0, s1, odd, h ? a1 : a0);
            }
            const float* wl = sW + 0 * WSZ + kt2 * 16 + 4 * tig;
#pragma unroll
            for (int nt = 0; nt < 16; nt++) {
                float4 b = *(const float4*)(wl + (nt * 8 + gq) * WSTRIDE);
                mma8(accA + nt * 4, a0, b.x, b.y);
                mma8(accA + nt * 4, a1, b.z, b.w);
            }
        }
        ln_relu(accA, sBias, tig);

        // ---- Layer 2 ----
#pragma unroll
        for (int i = 0; i < 64; i++) accB[i] = 0.f;
#pragma unroll
        for (int kt2 = 0; kt2 < 8; kt2++) {
            uint32_t a0[4], a1[4];
            mkA1(accA[8*kt2+0], accA[8*kt2+1], accA[8*kt2+2], accA[8*kt2+3],
                 s0, s1, odd, a0);
            mkA1(accA[8*kt2+4], accA[8*kt2+5], accA[8*kt2+6], accA[8*kt2+7],
                 s0, s1, odd, a1);
            const float* wl = sW + 1 * WSZ + kt2 * 16 + 4 * tig;
#pragma unroll
            for (int nt = 0; nt < 16; nt++) {
                float4 b = *(const float4*)(wl + (nt * 8 + gq) * WSTRIDE);
                mma8(accB + nt * 4, a0, b.x, b.y);
                mma8(accB + nt * 4, a1, b.z, b.w);
            }
        }
        ln_relu(accB, sBias + 3 * HH, tig);

        // ---- Layer 3 ----
#pragma unroll
        for (int i = 0; i < 64; i++) accA[i] = 0.f;
#pragma unroll
        for (int kt2 = 0; kt2 < 8; kt2++) {
            uint32_t a0[4], a1[4];
            mkA1(accB[8*kt2+0], accB[8*kt2+1], accB[8*kt2+2], accB[8*kt2+3],
                 s0, s1, odd, a0);
            mkA1(accB[8*kt2+4], accB[8*kt2+5], accB[8*kt2+6], accB[8*kt2+7],
                 s0, s1, odd, a1);
            const float* wl = sW + 2 * WSZ + kt2 * 16 + 4 * tig;
#pragma unroll
            for (int nt = 0; nt < 16; nt++) {
                float4 b = *(const float4*)(wl + (nt * 8 + gq) * WSTRIDE);
                mma8(accA + nt * 4, a0, b.x, b.y);
                mma8(accA + nt * 4, a1, b.z, b.w);
            }
        }

        // ---- epilogue: +b3, per-node sum/sumsq, store h3 ----
        const float* bb3 = sBias + 6 * HH;
        float sA = 0.f, sBr = 0.f, qA = 0.f, qB = 0.f;
#pragma unroll
        for (int nt = 0; nt < 16; nt++) {
            float2 bb = *(const float2*)(bb3 + nt * 8 + 2 * tig);
            accA[4*nt+0] += bb.x; accA[4*nt+1] += bb.y;
            accA[4*nt+2] += bb.x; accA[4*nt+3] += bb.y;
            sA += accA[4*nt+0] + accA[4*nt+1];
            qA += accA[4*nt+0]*accA[4*nt+0] + accA[4*nt+1]*accA[4*nt+1];
            sBr += accA[4*nt+2] + accA[4*nt+3];
            qB  += accA[4*nt+2]*accA[4*nt+2] + accA[4*nt+3]*accA[4*nt+3];
        }
        quadred(sA); quadred(qA); quadred(sBr); quadred(qB);
#pragma unroll
        for (int nt = 0; nt < 16; nt++) {
            size_t o = nt * 8 + 2 * tig;
            *(float2*)(d_h3 + rbase0 + o) = make_float2(accA[4*nt+0], accA[4*nt+1]);
            *(float2*)(d_h3 + rbase1 + o) = make_float2(accA[4*nt+2], accA[4*nt+3]);
        }
        if (tig == 0) {
            d_sn[R + gq]     = sA;  d_sq[R + gq]     = qA;
            d_sn[R + gq + 8] = sBr; d_sq[R + gq + 8] = qB;
        }
    }
}

// ============================================================
// K3: warp-cooperative per-graph reduction (one tile per warp,
//     single wave). Last block finalizes mean/rstd.
// ============================================================
__global__ void k3_stats(const int* __restrict__ bp) {
    const int nwarp = (gridDim.x * blockDim.x) >> 5;
    const int w0 = (blockIdx.x * blockDim.x + threadIdx.x) >> 5;
    const int lane = threadIdx.x & 31;

    for (int base = w0 * 32; base < NN; base += nwarp * 32) {
        int n = base + lane;
        bool valid = n < NN;
        int g = valid ? bp[n] : -1;
        float s = valid ? d_sn[n] : 0.f;
        float q = valid ? d_sq[n] : 0.f;
        int gref = __shfl_sync(0xffffffffu, g, 0);
        bool uni = __all_sync(0xffffffffu, (g == gref) || !valid);
        if (uni) {
            float c = (float)__popc(__ballot_sync(0xffffffffu, valid));
#pragma unroll
            for (int off = 16; off; off >>= 1) {
                s += __shfl_xor_sync(0xffffffffu, s, off);
                q += __shfl_xor_sync(0xffffffffu, q, off);
            }
            if (lane == 0 && (unsigned)gref < GG) {
                atomicAdd(&d_gbuf[gref], s);
                atomicAdd(&d_gbuf[GG + gref], q);
                atomicAdd(&d_gbuf[2 * GG + gref], c);
            }
        } else {
            if (valid && (unsigned)g < GG) {
                atomicAdd(&d_gbuf[g], s);
                atomicAdd(&d_gbuf[GG + g], q);
                atomicAdd(&d_gbuf[2 * GG + g], 1.0f);
            }
        }
    }

    __shared__ bool last;
    __threadfence();
    __syncthreads();
    if (threadIdx.x == 0) {
        unsigned* ticket = (unsigned*)&d_gbuf[3 * GG];
        last = (atomicAdd(ticket, 1u) == gridDim.x - 1);
    }
    __syncthreads();
    if (last && threadIdx.x < GG) {
        int g = threadIdx.x;
        float cnt  = d_gbuf[2 * GG + g];
        float norm = fmaxf(cnt * (float)HH, 1.0f);
        float mean = d_gbuf[g] / norm;
        float var  = d_gbuf[GG + g] / norm - mean * mean;
        d_gmean[g] = mean;
        d_grstd[g] = rsqrtf(var + 1e-5f);
    }
}

// ============================================================
// K4: graph-mode LayerNorm + affine + ReLU  (elementwise, 2 quads/thread)
// ============================================================
__global__ void k4_out(const int* __restrict__ bp,
                       const float* __restrict__ lnw,
                       const float* __restrict__ lnb,
                       float* __restrict__ out) {
    const int HALF = NN * HH / 8;           // quads per half
    int base = blockIdx.x * blockDim.x + threadIdx.x;
    if (base >= HALF) return;
#pragma unroll
    for (int rep = 0; rep < 2; rep++) {
        int idx = base + rep * HALF;
        int n = idx >> 5;
        int j = idx & 31;
        int g = bp[n];
        if ((unsigned)g >= GG) g = 0;
        float mean = d_gmean[g];
        float r    = d_grstd[g];
        float4 h = ((const float4*)d_h3)[idx];
        float4 w = ((const float4*)lnw)[j];
        float4 b = ((const float4*)lnb)[j];
        float4 o;
        o.x = fmaxf(fmaf((h.x - mean) * r, w.x, b.x), 0.f);
        o.y = fmaxf(fmaf((h.y - mean) * r, w.y, b.y), 0.f);
        o.z = fmaxf(fmaf((h.z - mean) * r, w.z, b.z), 0.f);
        o.w = fmaxf(fmaf((h.w - mean) * r, w.w, b.w), 0.f);
        ((float4*)out)[idx] = o;
    }
}

// ============================================================
// host entry
// ============================================================
extern "C" void kernel_launch(void* const* d_in, const int* in_sizes, int n_in,
                              void* d_out, int out_size) {
    const float* node = (const float*)d_in[0];
    const int*   ei   = (const int*)d_in[1];
    const int*   bp   = (const int*)d_in[3];
    const float* eps  = (const float*)d_in[4];
    const float* W1 = (const float*)d_in[5],  *b1 = (const float*)d_in[6];
    const float* g1 = (const float*)d_in[7],  *be1 = (const float*)d_in[8];
    const float* W2 = (const float*)d_in[9],  *b2 = (const float*)d_in[10];
    const float* g2 = (const float*)d_in[11], *be2 = (const float*)d_in[12];
    const float* W3 = (const float*)d_in[13], *b3 = (const float*)d_in[14];
    const float* lnw = (const float*)d_in[15], *lnb = (const float*)d_in[16];
    float* out = (float*)d_out;

    void *cntp, *gbufp;
    cudaGetSymbolAddress(&cntp,  d_cnt);
    cudaGetSymbolAddress(&gbufp, d_gbuf);
    cudaMemsetAsync(cntp,  0, NN * sizeof(int));
    cudaMemsetAsync(gbufp, 0, (3 * GG + 1) * sizeof(float));

    k0_zero<<<1, 64>>>();                              // launch 3 (shifts ncu window)
    k1b_bucket<<<(EE + 255) / 256, 256>>>(ei);         // launch 4
    k1c_gather<<<(NN * 32 + 255) / 256, 256>>>(node, eps); // launch 5

    cudaFuncSetAttribute(k2_mma, cudaFuncAttributeMaxDynamicSharedMemorySize, (int)K2_SMEM_BYTES);
    k2_mma<<<148, 256, K2_SMEM_BYTES>>>(W1, b1, g1, be1, W2, b2, g2, be2, W3, b3); // launch 6 -> profiled

    k3_stats<<<391, 256>>>(bp);

    k4_out<<<(NN * HH / 8 + 255) / 256, 256>>>(bp, lnw, lnb, out);
}